// round 13
// baseline (speedup 1.0000x reference)
#include <cuda_runtime.h>
#include <cuda_bf16.h>
#include <cstdint>
#include <cstddef>

// Problem: VQ-VAE quantizer
// inputs: (32, 64, 64, 64) f32 NCHW ; emb_weight: (512, 64) f32
// Outputs (f32): loss(1) | quantized(8388608) | encoding_indices(131072) | perplexity(1) | codes(131072)
#define NB   32
#define NC   64
#define NHW  4096
#define NROW 131072
#define NK   512

#define OFF_LOSS  0
#define OFF_Q     1
#define OFF_IDX   8388609
#define OFF_PERP  8519681
#define OFF_CODES 8519682

#define THETA 0.01f

// Code split: codes 0..191 via tensor pipe (24/warp), 192..511 via fma pipe (40/warp)
#define HC 24
#define FC 40
#define NTC 192      // total tensor codes
#define NFC 320      // total fma codes

typedef unsigned long long ULL;

// ---------------------------------------------------------------------------
// PTX helpers — baseline ISA only (ldmatrix sm_75+, mma.sync bf16 sm_80+,
// fma.rn.f32x2 is plain PTX on Blackwell targets)
// ---------------------------------------------------------------------------
__device__ __forceinline__ uint32_t smem_to_u32(const void* p) {
    uint32_t a;
    asm("{ .reg .u64 t; cvta.to.shared.u64 t, %1; cvt.u32.u64 %0, t; }" : "=r"(a) : "l"(p));
    return a;
}
#define LDSM_X4(r, a) \
    asm volatile("ldmatrix.sync.aligned.m8n8.x4.shared.b16 {%0,%1,%2,%3}, [%4];" \
        : "=r"((r)[0]), "=r"((r)[1]), "=r"((r)[2]), "=r"((r)[3]) : "r"(a))
#define LDSM_X2(r, a) \
    asm volatile("ldmatrix.sync.aligned.m8n8.x2.shared.b16 {%0,%1}, [%2];" \
        : "=r"((r)[0]), "=r"((r)[1]) : "r"(a))
#define MMA16816(d, a, b) \
    asm volatile("mma.sync.aligned.m16n8k16.row.col.f32.bf16.bf16.f32 " \
        "{%0,%1,%2,%3}, {%4,%5,%6,%7}, {%8,%9}, {%0,%1,%2,%3};" \
        : "+f"((d)[0]), "+f"((d)[1]), "+f"((d)[2]), "+f"((d)[3]) \
        : "r"((a)[0]), "r"((a)[1]), "r"((a)[2]), "r"((a)[3]), \
          "r"((b)[0]), "r"((b)[1]))

__device__ __forceinline__ ULL f32x2_fma(ULL a, ULL b, ULL c) {
    ULL d;
    asm("fma.rn.f32x2 %0, %1, %2, %3;" : "=l"(d) : "l"(a), "l"(b), "l"(c));
    return d;
}
__device__ __forceinline__ ULL f32x2_bcast(float v) {
    ULL r;
    asm("mov.b64 %0, {%1, %2};" : "=l"(r) : "f"(v), "f"(v));
    return r;
}
__device__ __forceinline__ float2 f32x2_unpack(ULL v) {
    float2 r;
    asm("mov.b64 {%0, %1}, %2;" : "=f"(r.x), "=f"(r.y) : "l"(v));
    return r;
}

// ---------------------------------------------------------------------------
// Scratch
// ---------------------------------------------------------------------------
__device__ int            g_idx[NROW];
__device__ float          g_counts[NK];
__device__ float          g_hn[NK];          // 0.5 * ||e||^2
__device__ float          g_rowd[NROW];
__device__ int            g_flaglist[NROW];
__device__ int            g_nflag;
__device__ __nv_bfloat16  g_ehi[NK * NC];    // codebook bf16 hi, K-major
__device__ __nv_bfloat16  g_elo[NK * NC];    // codebook bf16 lo (residual)

// SMEM layout (bytes)
#define RSTRIDE   144                      // A/B bf16 tile row stride
#define ESTRIDE   320                      // es floats per k-row (320 fma codes)
#define SM_AHI    0                        // 128 x 144  = 18432
#define SM_ALO    18432                    // 128 x 144
#define SM_BHI    36864                    // 192 x 144  = 27648
#define SM_BLO    64512                    // 192 x 144
#define SM_ES     92160                    // 64 x 320 f32 = 81920 (k-major)
#define SM_XS     174080                   // 64 x 128 f32 = 32768 (k-major)
#define SM_HN     206848                   // 512 f32 = 2048
#define SM_M1     208896                   // 16 x 128 f32 = 8192
#define SM_M2     217088                   // 16 x 128 f32
#define SM_MI     225280                   // 16 x 128 i16 = 4096
#define SM_TOTAL  229376

// ---------------------------------------------------------------------------
// Kernel 0: init
// ---------------------------------------------------------------------------
__global__ void vq_init(const float* __restrict__ emb) {
    int t = threadIdx.x;               // 512 threads
    const float4* e = (const float4*)(emb + t * NC);
    float s = 0.f;
#pragma unroll
    for (int i = 0; i < 16; i++) {
        float4 v = e[i];
        s += v.x * v.x + v.y * v.y + v.z * v.z + v.w * v.w;
    }
    g_hn[t] = 0.5f * s;
    g_counts[t] = 0.f;
    if (t == 0) g_nflag = 0;
    for (int i = t; i < NK * NC; i += 512) {
        float v = emb[i];
        __nv_bfloat16 h = __float2bfloat16(v);
        g_ehi[i] = h;
        g_elo[i] = __float2bfloat16(v - __bfloat162float(h));
    }
}

// ---------------------------------------------------------------------------
// Tensor phase: warp w computes codes [w*24, w*24+24) for all 128 rows using
// mma.sync bf16 3-split (xh*eh + xh*el + xl*eh). Writes top2 to slot w.
// ---------------------------------------------------------------------------
__device__ __forceinline__ void tensor_phase(
    uint32_t sb, char* smem, int w, int lane,
    const float* hn_s, float* m1, float* m2, short* mi)
{
    const int cbase = w * HC;
    const uint32_t a_lane = (uint32_t)((lane & 15) * RSTRIDE + (lane >> 4) * 16);
    const uint32_t b_lane = (uint32_t)((cbase + (lane & 7)) * RSTRIDE + ((lane >> 3) & 1) * 16);

    // hoist all B-hi fragments (loaded once)
    uint32_t bh[3][4][2];
#pragma unroll
    for (int nt = 0; nt < 3; nt++)
#pragma unroll
        for (int k = 0; k < 4; k++)
            LDSM_X2(bh[nt][k], sb + SM_BHI + b_lane + (uint32_t)(nt * 8 * RSTRIDE) + k * 32);

    float acc[8][3][4];
#pragma unroll
    for (int mt = 0; mt < 8; mt++)
#pragma unroll
        for (int nt = 0; nt < 3; nt++)
#pragma unroll
            for (int c = 0; c < 4; c++) acc[mt][nt][c] = 0.f;

#pragma unroll
    for (int k = 0; k < 4; k++) {
        uint32_t blo[3][2];
#pragma unroll
        for (int nt = 0; nt < 3; nt++)
            LDSM_X2(blo[nt], sb + SM_BLO + b_lane + (uint32_t)(nt * 8 * RSTRIDE) + k * 32);
#pragma unroll
        for (int mt = 0; mt < 8; mt++) {
            uint32_t ah[4], al[4];
            LDSM_X4(ah, sb + SM_AHI + (uint32_t)(mt * 16 * RSTRIDE) + a_lane + k * 32);
            LDSM_X4(al, sb + SM_ALO + (uint32_t)(mt * 16 * RSTRIDE) + a_lane + k * 32);
#pragma unroll
            for (int nt = 0; nt < 3; nt++) {
                MMA16816(acc[mt][nt], ah, bh[nt][k]);
                MMA16816(acc[mt][nt], al, bh[nt][k]);
                MMA16816(acc[mt][nt], ah, blo[nt]);
            }
        }
    }

    // epilogue: top2 per row over this warp's 24 codes
#pragma unroll
    for (int mt = 0; mt < 8; mt++) {
#pragma unroll
        for (int h = 0; h < 2; h++) {
            int row = mt * 16 + h * 8 + (lane >> 2);
            float bv1 = -3.4e38f, bv2 = -3.4e38f;
            int bi = 0;
#pragma unroll
            for (int nt = 0; nt < 3; nt++) {
                int code = cbase + nt * 8 + 2 * (lane & 3);
                float v0 = acc[mt][nt][h * 2 + 0] - hn_s[code];
                float v1 = acc[mt][nt][h * 2 + 1] - hn_s[code + 1];
                if (v0 > bv1) { bv2 = bv1; bv1 = v0; bi = code; }
                else if (v0 > bv2) bv2 = v0;
                if (v1 > bv1) { bv2 = bv1; bv1 = v1; bi = code + 1; }
                else if (v1 > bv2) bv2 = v1;
            }
#pragma unroll
            for (int off = 1; off <= 2; off <<= 1) {
                float o1 = __shfl_xor_sync(0xffffffffu, bv1, off);
                float o2 = __shfl_xor_sync(0xffffffffu, bv2, off);
                int   oi = __shfl_xor_sync(0xffffffffu, bi, off);
                if (o1 > bv1 || (o1 == bv1 && oi < bi)) {
                    bv2 = fmaxf(bv1, o2); bv1 = o1; bi = oi;
                } else {
                    bv2 = fmaxf(bv2, o1);
                }
            }
            if ((lane & 3) == 0) {
                m1[w * 128 + row] = bv1;
                m2[w * 128 + row] = bv2;
                mi[w * 128 + row] = (short)bi;
            }
        }
    }
}

// ---------------------------------------------------------------------------
// FMA phase: warp w computes codes [192 + w*40, +40) for all 128 rows using
// exact fp32 fma.rn.f32x2 (code-pair packed). Writes top2 to slot 8+w.
// ---------------------------------------------------------------------------
__device__ __forceinline__ void fma_phase(
    char* smem, int w, int lane,
    const float* hn_s, float* m1, float* m2, short* mi)
{
    const int pr = lane & 15;          // row pair within 32-row pass
    const int ch = lane >> 4;          // code half: 20 codes each
    const int fb = NTC + w * FC + ch * 20;   // first code of this lane's 20
    const float* xs = (const float*)(smem + SM_XS);
    const char*  esb = smem + SM_ES + (size_t)(w * FC + ch * 20) * 4;

    for (int mt2 = 0; mt2 < 4; mt2++) {
        ULL a0[10], a1[10];
#pragma unroll
        for (int cp = 0; cp < 10; cp++) { a0[cp] = 0ull; a1[cp] = 0ull; }

        const int r0 = mt2 * 32 + pr * 2;
#pragma unroll 4
        for (int k = 0; k < 64; k++) {
            ULL xv = *(const ULL*)&xs[k * 128 + r0];
            float2 xp = f32x2_unpack(xv);
            ULL x00 = f32x2_bcast(xp.x);
            ULL x11 = f32x2_bcast(xp.y);
            const ULL* ev = (const ULL*)(esb + (size_t)k * (ESTRIDE * 4));
#pragma unroll
            for (int cp = 0; cp < 10; cp++) {
                ULL e = ev[cp];
                a0[cp] = f32x2_fma(x00, e, a0[cp]);
                a1[cp] = f32x2_fma(x11, e, a1[cp]);
            }
        }

        // per-row top2 over 20 codes
        float b1r0 = -3.4e38f, b2r0 = -3.4e38f, b1r1 = -3.4e38f, b2r1 = -3.4e38f;
        int i0 = 0, i1 = 0;
#pragma unroll
        for (int cp = 0; cp < 10; cp++) {
            int c0 = fb + 2 * cp;
            float h0 = hn_s[c0], h1 = hn_s[c0 + 1];
            float2 s0 = f32x2_unpack(a0[cp]);
            float2 s1 = f32x2_unpack(a1[cp]);
            float u = s0.x - h0, v = s0.y - h1;
            if (u > b1r0) { b2r0 = b1r0; b1r0 = u; i0 = c0; }
            else if (u > b2r0) b2r0 = u;
            if (v > b1r0) { b2r0 = b1r0; b1r0 = v; i0 = c0 + 1; }
            else if (v > b2r0) b2r0 = v;
            u = s1.x - h0; v = s1.y - h1;
            if (u > b1r1) { b2r1 = b1r1; b1r1 = u; i1 = c0; }
            else if (u > b2r1) b2r1 = u;
            if (v > b1r1) { b2r1 = b1r1; b1r1 = v; i1 = c0 + 1; }
            else if (v > b2r1) b2r1 = v;
        }
        // merge the two code-halves (lanes l and l^16 share rows)
        {
            float o1 = __shfl_xor_sync(0xffffffffu, b1r0, 16);
            float o2 = __shfl_xor_sync(0xffffffffu, b2r0, 16);
            int   oi = __shfl_xor_sync(0xffffffffu, i0, 16);
            if (o1 > b1r0 || (o1 == b1r0 && oi < i0)) { b2r0 = fmaxf(b1r0, o2); b1r0 = o1; i0 = oi; }
            else { b2r0 = fmaxf(b2r0, o1); }
            o1 = __shfl_xor_sync(0xffffffffu, b1r1, 16);
            o2 = __shfl_xor_sync(0xffffffffu, b2r1, 16);
            oi = __shfl_xor_sync(0xffffffffu, i1, 16);
            if (o1 > b1r1 || (o1 == b1r1 && oi < i1)) { b2r1 = fmaxf(b1r1, o2); b1r1 = o1; i1 = oi; }
            else { b2r1 = fmaxf(b2r1, o1); }
        }
        if (lane < 16) {
            int slot = 8 + w;
            m1[slot * 128 + r0] = b1r0;  m2[slot * 128 + r0] = b2r0;  mi[slot * 128 + r0] = (short)i0;
            m1[slot * 128 + r0 + 1] = b1r1; m2[slot * 128 + r0 + 1] = b2r1; mi[slot * 128 + r0 + 1] = (short)i1;
        }
    }
}

// ---------------------------------------------------------------------------
// Kernel 1: dual-pipe argmin. CTA = 128 rows x 512 codes, 256 threads.
// Warps 0-3: tensor then fma; warps 4-7: fma then tensor -> each SMSP keeps
// both the tensor pipe and the fma pipe busy concurrently.
// ---------------------------------------------------------------------------
__global__ void __launch_bounds__(256, 1)
vq_argmin(const float* __restrict__ x_in, const float* __restrict__ emb) {
    extern __shared__ char smem[];
    const uint32_t sb = smem_to_u32(smem);
    float* hn_s = (float*)(smem + SM_HN);
    float* m1   = (float*)(smem + SM_M1);
    float* m2   = (float*)(smem + SM_M2);
    short* mi   = (short*)(smem + SM_MI);
    float* xs   = (float*)(smem + SM_XS);
    float* es   = (float*)(smem + SM_ES);

    const int tid  = threadIdx.x;
    const int w    = tid >> 5;
    const int lane = tid & 31;
    const int n0   = blockIdx.x * 128;
    const int b    = n0 >> 12;
    const int hw0  = n0 & 4095;

    // ---- prologue: x tile -> xs fp32 (k-major) + A hi/lo bf16 tiles
    const float* xbase = x_in + (size_t)b * (NC * NHW) + hw0;
    for (int i = tid; i < 64 * 128; i += 256) {
        int c = i >> 7, m = i & 127;                    // coalesced over m
        float v = xbase[(size_t)c * NHW + m];
        xs[c * 128 + m] = v;
        __nv_bfloat16 h = __float2bfloat16(v);
        __nv_bfloat16 l = __float2bfloat16(v - __bfloat162float(h));
        *(__nv_bfloat16*)(smem + SM_AHI + m * RSTRIDE + c * 2) = h;
        *(__nv_bfloat16*)(smem + SM_ALO + m * RSTRIDE + c * 2) = l;
    }
    // ---- tensor codebook (codes 0..191) hi/lo bf16 tiles
    {
        const uint32_t* ehi = (const uint32_t*)g_ehi;
        const uint32_t* elo = (const uint32_t*)g_elo;
        for (int i = tid; i < NTC * 32; i += 256) {
            int code = i >> 5, cw = i & 31;
            *(uint32_t*)(smem + SM_BHI + code * RSTRIDE + cw * 4) = ehi[i];
            *(uint32_t*)(smem + SM_BLO + code * RSTRIDE + cw * 4) = elo[i];
        }
    }
    // ---- fma codebook (codes 192..511) fp32, k-major transposed.
    // mapping: lanes hold consecutive codes -> conflict-free smem writes.
    {
        const float4* e4 = (const float4*)emb;
        for (int i = tid; i < NFC * 16; i += 256) {
            int l2  = i & 31;                 // code within 32-group
            int kq  = (i >> 5) & 15;          // which float4 of the row
            int blk = i >> 9;                 // 32-code block (0..9)
            int c2  = blk * 32 + l2;          // fma-code index 0..319
            float4 v = e4[(size_t)(NTC + c2) * 16 + kq];
            es[(4 * kq + 0) * ESTRIDE + c2] = v.x;
            es[(4 * kq + 1) * ESTRIDE + c2] = v.y;
            es[(4 * kq + 2) * ESTRIDE + c2] = v.z;
            es[(4 * kq + 3) * ESTRIDE + c2] = v.w;
        }
    }
    for (int i = tid; i < NK; i += 256) hn_s[i] = g_hn[i];
    __syncthreads();

    // ---- dual-pipe phases (no barriers inside; warps independent)
    if (w < 4) {
        tensor_phase(sb, smem, w, lane, hn_s, m1, m2, mi);
        fma_phase(smem, w, lane, hn_s, m1, m2, mi);
    } else {
        fma_phase(smem, w, lane, hn_s, m1, m2, mi);
        tensor_phase(sb, smem, w, lane, hn_s, m1, m2, mi);
    }
    __syncthreads();

    // ---- final per-row merge across 16 slots (ascending code ranges)
    if (tid < 128) {
        int row = tid;
        float bv1 = m1[row], bv2 = m2[row];
        int   bi  = mi[row];
#pragma unroll
        for (int g = 1; g < 16; g++) {
            float o1 = m1[g * 128 + row];
            float o2 = m2[g * 128 + row];
            if (o1 > bv1) { bv2 = fmaxf(bv1, o2); bv1 = o1; bi = mi[g * 128 + row]; }
            else          { bv2 = fmaxf(bv2, o1); }
        }

        // exact fp32 d = ||x - e_best||^2 (xs is exact fp32)
        const float* e = emb + bi * NC;
        float d = 0.f;
#pragma unroll
        for (int c = 0; c < NC; c++) {
            float t = xs[c * 128 + row] - e[c];
            d += t * t;
        }
        int n = n0 + row;
        g_idx[n]  = bi;
        g_rowd[n] = d;
        atomicAdd(&g_counts[bi], 1.0f);
        if (bv1 - bv2 < THETA) {
            int p = atomicAdd(&g_nflag, 1);
            g_flaglist[p] = n;
        }
    }
}

// ---------------------------------------------------------------------------
// Kernel 2: fp32 fixup for flagged (small-margin) rows. Exact argmin.
// ---------------------------------------------------------------------------
__global__ void __launch_bounds__(128, 8)
vq_fixup(const float* __restrict__ x_in, const float* __restrict__ emb) {
    __shared__ float xrow[64];
    __shared__ float sv[128];
    __shared__ int   si[128];
    int t = threadIdx.x;
    int nf = g_nflag;
    for (int f = blockIdx.x; f < nf; f += gridDim.x) {
        int n = g_flaglist[f];
        int b = n >> 12, hw = n & 4095;
        if (t < 64)
            xrow[t] = x_in[(size_t)b * (NC * NHW) + (size_t)t * NHW + hw];
        __syncthreads();

        float best = -3.4e38f; int bi = 0;
        for (int kk = 0; kk < 4; kk++) {
            int code = kk * 128 + t;
            const float* e = emb + code * NC;
            float dot = 0.f;
#pragma unroll
            for (int c = 0; c < 64; c++) dot += xrow[c] * e[c];
            float s = dot - g_hn[code];
            if (s > best) { best = s; bi = code; }
        }
        sv[t] = best; si[t] = bi;
        __syncthreads();
#pragma unroll
        for (int o = 64; o >= 1; o >>= 1) {
            if (t < o) {
                float a = sv[t], c2 = sv[t + o];
                if (c2 > a || (c2 == a && si[t + o] < si[t])) { sv[t] = c2; si[t] = si[t + o]; }
            }
            __syncthreads();
        }
        if (t == 0) {
            int newi = si[0], old = g_idx[n];
            if (newi != old) {
                atomicAdd(&g_counts[old], -1.0f);
                atomicAdd(&g_counts[newi], 1.0f);
                g_idx[n] = newi;
            }
            const float* e = emb + newi * NC;
            float d = 0.f;
#pragma unroll
            for (int c = 0; c < 64; c++) { float tt = xrow[c] - e[c]; d += tt * tt; }
            g_rowd[n] = d;
        }
        __syncthreads();
    }
}

// ---------------------------------------------------------------------------
// Kernel 3: gather quantized output (NCHW) + index outputs (L2-direct, no smem)
// ---------------------------------------------------------------------------
__global__ void __launch_bounds__(256)
vq_gather(const float* __restrict__ emb, float* __restrict__ out) {
    int n = blockIdx.x * 256 + threadIdx.x;
    int idx = g_idx[n];
    const float4* cr = (const float4*)(emb + (size_t)idx * NC);

    int b = n >> 12, hw = n & 4095;
    float* qb = out + OFF_Q + (size_t)b * (NC * NHW) + hw;
#pragma unroll
    for (int q = 0; q < 16; q++) {
        float4 v = __ldg(cr + q);
        qb[(size_t)(4 * q + 0) * NHW] = v.x;
        qb[(size_t)(4 * q + 1) * NHW] = v.y;
        qb[(size_t)(4 * q + 2) * NHW] = v.z;
        qb[(size_t)(4 * q + 3) * NHW] = v.w;
    }
    float fidx = (float)idx;
    out[OFF_IDX + n]   = fidx;
    out[OFF_CODES + n] = fidx;
}

// ---------------------------------------------------------------------------
// Kernel 4: finalize loss + perplexity (deterministic fixed-order sums)
// ---------------------------------------------------------------------------
__global__ void vq_finalize(float* __restrict__ out) {
    __shared__ float sp[512];
    __shared__ float sl[512];
    int t = threadIdx.x;
    float p = g_counts[t] * (1.0f / (float)NROW);
    sp[t] = p * logf(p + 1e-10f);
    float s = 0.f;
    for (int i = 0; i < NROW / 512; i++) s += g_rowd[i * 512 + t];
    sl[t] = s;
    __syncthreads();
#pragma unroll
    for (int o = 256; o >= 1; o >>= 1) {
        if (t < o) { sp[t] += sp[t + o]; sl[t] += sl[t + o]; }
        __syncthreads();
    }
    if (t == 0) {
        out[OFF_PERP] = expf(-sp[0]);
        out[OFF_LOSS] = 0.25f * sl[0] * (1.0f / 8388608.0f);
    }
}

// ---------------------------------------------------------------------------
// Launch
// ---------------------------------------------------------------------------
extern "C" void kernel_launch(void* const* d_in, const int* in_sizes, int n_in,
                              void* d_out, int out_size) {
    const float* x = (const float*)d_in[0];
    const float* e = (const float*)d_in[1];
    if (n_in >= 2 && in_sizes[0] == NK * NC) {
        const float* tmp = x; x = e; e = tmp;
    }
    float* out = (float*)d_out;

    cudaFuncSetAttribute(vq_argmin, cudaFuncAttributeMaxDynamicSharedMemorySize, SM_TOTAL);

    vq_init<<<1, 512>>>(e);
    vq_argmin<<<NROW / 128, 256, SM_TOTAL>>>(x, e);
    vq_fixup<<<1024, 128>>>(x, e);
    vq_gather<<<NROW / 256, 256>>>(e, out);
    vq_finalize<<<1, 512>>>(out);
}

// round 14
// speedup vs baseline: 1.6967x; 1.6967x over previous
#include <cuda_runtime.h>
#include <cuda_bf16.h>
#include <cstdint>
#include <cstddef>

// Problem: VQ-VAE quantizer
// inputs: (32, 64, 64, 64) f32 NCHW ; emb_weight: (512, 64) f32
// Outputs (f32): loss(1) | quantized(8388608) | encoding_indices(131072) | perplexity(1) | codes(131072)
#define NB   32
#define NC   64
#define NHW  4096
#define NROW 131072
#define NK   512

#define OFF_LOSS  0
#define OFF_Q     1
#define OFF_IDX   8388609
#define OFF_PERP  8519681
#define OFF_CODES 8519682

typedef unsigned long long ULL;

// ---------------------------------------------------------------------------
// f32x2 packed-math helpers (plain PTX on Blackwell targets)
// ---------------------------------------------------------------------------
__device__ __forceinline__ ULL f32x2_fma(ULL a, ULL b, ULL c) {
    ULL d;
    asm("fma.rn.f32x2 %0, %1, %2, %3;" : "=l"(d) : "l"(a), "l"(b), "l"(c));
    return d;
}
__device__ __forceinline__ ULL f32x2_bcast(float v) {
    ULL r;
    asm("mov.b64 %0, {%1, %2};" : "=l"(r) : "f"(v), "f"(v));
    return r;
}
__device__ __forceinline__ float2 f32x2_unpack(ULL v) {
    float2 r;
    asm("mov.b64 {%0, %1}, %2;" : "=f"(r.x), "=f"(r.y) : "l"(v));
    return r;
}

// ---------------------------------------------------------------------------
// Scratch
// ---------------------------------------------------------------------------
__device__ int   g_idx[NROW];
__device__ float g_counts[NK];
__device__ float g_hn[NK];        // 0.5 * ||e||^2
__device__ float g_rowd[NROW];    // per-row ||x - e_best||^2 (exact fp32)

// ---------------------------------------------------------------------------
// Kernel 0: init — half-norms of codes, zero histogram
// ---------------------------------------------------------------------------
__global__ void vq_init(const float* __restrict__ emb) {
    int t = threadIdx.x;               // 512 threads
    const float4* e = (const float4*)(emb + t * NC);
    float s = 0.f;
#pragma unroll
    for (int i = 0; i < 16; i++) {
        float4 v = e[i];
        s += v.x * v.x + v.y * v.y + v.z * v.z + v.w * v.w;
    }
    g_hn[t] = 0.5f * s;
    g_counts[t] = 0.f;
}

// ---------------------------------------------------------------------------
// Kernel 1: exact fp32 FFMA2 argmin.
// CTA = 64 rows x 512 codes, 128 threads, smem 49.5KB -> 4 CTAs/SM (16 warps).
// Thread tile: 8 rows x 8 codes, rows accumulated pairwise via fma.rn.f32x2.
// Code tiles of 128 (4 tiles cover K=512). C=64 is the full reduction dim.
// ---------------------------------------------------------------------------
__global__ void __launch_bounds__(128, 4)
vq_argmin(const float* __restrict__ x_in, const float* __restrict__ emb) {
    extern __shared__ float sm[];
    float (*xs)[64]  = (float (*)[64])sm;                  // [64][64]  = 16 KB
    float (*es)[132] = (float (*)[132])(sm + 64 * 64);     // [64][132] = 33 KB (padded)
    float* hn_s = sm + 64 * 64 + 64 * 132;                 // [128]
    float* rvs  = (float*)es;                              // overlay: 16*64 floats
    int*   ris  = ((int*)es) + 16 * 64;                    // overlay: 16*64 ints

    const int tid = threadIdx.x;
    const int rg  = tid & 7;           // row group 0..7 (8 rows: pairs {2rg+16j, +1})
    const int cg  = tid >> 3;          // code group 0..15 (8 codes)
    const int n0  = blockIdx.x * 64;
    const int b   = n0 >> 12;
    const int hw0 = n0 & 4095;

    // Load x tile transposed: xs[c][m] = inputs[b][c][hw0+m]  (coalesced)
    const float* xbase = x_in + (size_t)b * (NC * NHW) + hw0;
    for (int i = tid; i < 64 * 64; i += 128) {
        int c = i >> 6, m = i & 63;
        xs[c][m] = xbase[(size_t)c * NHW + m];
    }

    float bestv[8];
    int   besti[8];
#pragma unroll
    for (int j = 0; j < 8; j++) { bestv[j] = -3.4e38f; besti[j] = 0; }

    for (int ct = 0; ct < 4; ct++) {
        __syncthreads();  // protect es/hn_s from previous tile's readers
        // Load 128-code tile transposed: es[c][code]
        const float* ebase = emb + (size_t)ct * 128 * NC;
        for (int i = tid; i < 128 * 64; i += 128) {
            es[i & 63][i >> 6] = ebase[i];
        }
        if (tid < 128) hn_s[tid] = g_hn[ct * 128 + tid];
        __syncthreads();

        ULL acc[4][8];
#pragma unroll
        for (int j = 0; j < 4; j++)
#pragma unroll
            for (int c = 0; c < 8; c++) acc[j][c] = 0ull;

#pragma unroll 8
        for (int k = 0; k < 64; k++) {
            ULL xv[4];
#pragma unroll
            for (int j = 0; j < 4; j++)
                xv[j] = *(const ULL*)&xs[k][2 * rg + 16 * j];   // (row, row+1) pair
            float4 ea = *(const float4*)&es[k][cg * 8];
            float4 eb = *(const float4*)&es[k][cg * 8 + 4];
            ULL ep[8];
            ep[0] = f32x2_bcast(ea.x); ep[1] = f32x2_bcast(ea.y);
            ep[2] = f32x2_bcast(ea.z); ep[3] = f32x2_bcast(ea.w);
            ep[4] = f32x2_bcast(eb.x); ep[5] = f32x2_bcast(eb.y);
            ep[6] = f32x2_bcast(eb.z); ep[7] = f32x2_bcast(eb.w);
#pragma unroll
            for (int j = 0; j < 4; j++)
#pragma unroll
                for (int c = 0; c < 8; c++)
                    acc[j][c] = f32x2_fma(xv[j], ep[c], acc[j][c]);
        }

        // Per-tile epilogue: score = dot - 0.5||e||^2 ; running argmax
        // (ascending code order -> reference first-min tie semantics)
#pragma unroll
        for (int c = 0; c < 8; c++) {
            float h = hn_s[cg * 8 + c];
            int code = ct * 128 + cg * 8 + c;
#pragma unroll
            for (int j = 0; j < 4; j++) {
                float2 a = f32x2_unpack(acc[j][c]);
                float s0 = a.x - h, s1 = a.y - h;
                if (s0 > bestv[2 * j])     { bestv[2 * j]     = s0; besti[2 * j]     = code; }
                if (s1 > bestv[2 * j + 1]) { bestv[2 * j + 1] = s1; besti[2 * j + 1] = code; }
            }
        }
    }

    __syncthreads();  // all done reading es -> safe to overlay reduce arrays
#pragma unroll
    for (int j = 0; j < 4; j++) {
#pragma unroll
        for (int p = 0; p < 2; p++) {
            int row = 2 * rg + 16 * j + p;
            rvs[cg * 64 + row] = bestv[2 * j + p];
            ris[cg * 64 + row] = besti[2 * j + p];
        }
    }
    __syncthreads();

    if (tid < 64) {
        int row = tid;
        float bv = rvs[row];
        int   bi = ris[row];
#pragma unroll
        for (int g = 1; g < 16; g++) {
            float v = rvs[g * 64 + row];
            if (v > bv) { bv = v; bi = ris[g * 64 + row]; }
        }
        // ||x||^2 for this row (xs intact)
        float xn = 0.f;
#pragma unroll
        for (int k = 0; k < 64; k++) { float xv = xs[k][row]; xn += xv * xv; }
        int n = n0 + row;
        g_idx[n]  = bi;
        g_rowd[n] = xn - 2.f * bv;       // = ||x - e_best||^2 (exact fp32 scores)
        atomicAdd(&g_counts[bi], 1.0f);  // integer-valued float adds: exact
    }
}

// ---------------------------------------------------------------------------
// Kernel 2: gather quantized output (NCHW) + index outputs (L2-direct, no smem)
// ---------------------------------------------------------------------------
__global__ void __launch_bounds__(256)
vq_gather(const float* __restrict__ emb, float* __restrict__ out) {
    int n = blockIdx.x * 256 + threadIdx.x;
    int idx = g_idx[n];
    const float4* cr = (const float4*)(emb + (size_t)idx * NC);

    int b = n >> 12, hw = n & 4095;
    float* qb = out + OFF_Q + (size_t)b * (NC * NHW) + hw;
#pragma unroll
    for (int q = 0; q < 16; q++) {
        float4 v = __ldg(cr + q);
        qb[(size_t)(4 * q + 0) * NHW] = v.x;   // consecutive threads -> consecutive hw
        qb[(size_t)(4 * q + 1) * NHW] = v.y;
        qb[(size_t)(4 * q + 2) * NHW] = v.z;
        qb[(size_t)(4 * q + 3) * NHW] = v.w;
    }
    float fidx = (float)idx;
    out[OFF_IDX + n]   = fidx;
    out[OFF_CODES + n] = fidx;
}

// ---------------------------------------------------------------------------
// Kernel 3: finalize loss + perplexity (deterministic fixed-order sums)
// ---------------------------------------------------------------------------
__global__ void vq_finalize(float* __restrict__ out) {
    __shared__ float sp[512];
    __shared__ float sl[512];
    int t = threadIdx.x;
    float p = g_counts[t] * (1.0f / (float)NROW);
    sp[t] = p * logf(p + 1e-10f);
    float s = 0.f;
    for (int i = 0; i < NROW / 512; i++) s += g_rowd[i * 512 + t];
    sl[t] = s;
    __syncthreads();
#pragma unroll
    for (int o = 256; o >= 1; o >>= 1) {
        if (t < o) { sp[t] += sp[t + o]; sl[t] += sl[t + o]; }
        __syncthreads();
    }
    if (t == 0) {
        out[OFF_PERP] = expf(-sp[0]);
        out[OFF_LOSS] = 0.25f * sl[0] * (1.0f / 8388608.0f);  // BETA * mean over N*C
    }
}

// ---------------------------------------------------------------------------
// Launch
// ---------------------------------------------------------------------------
extern "C" void kernel_launch(void* const* d_in, const int* in_sizes, int n_in,
                              void* d_out, int out_size) {
    const float* x = (const float*)d_in[0];
    const float* e = (const float*)d_in[1];
    if (n_in >= 2 && in_sizes[0] == NK * NC) {
        const float* tmp = x; x = e; e = tmp;
    }
    float* out = (float*)d_out;

    const int SMEM1 = (64 * 64 + 64 * 132 + 128) * (int)sizeof(float);  // 50688 B
    cudaFuncSetAttribute(vq_argmin, cudaFuncAttributeMaxDynamicSharedMemorySize, SMEM1);

    vq_init<<<1, 512>>>(e);
    vq_argmin<<<NROW / 64, 128, SMEM1>>>(x, e);
    vq_gather<<<NROW / 256, 256>>>(e, out);
    vq_finalize<<<1, 512>>>(out);
}